// round 7
// baseline (speedup 1.0000x reference)
#include <cuda_runtime.h>
#include <math.h>

// x is (B, F) row-major fp32
#define B_ROWS 32768
#define F_COLS 1024
#define F4     (F_COLS / 4)            // 256 float4 per row
#define NBLK   592                     // 148 SMs x 4 CTAs -> perfectly balanced
#define CHUNK_ROWS 8
#define NCHUNK (B_ROWS / CHUNK_ROWS)   // 4096 chunks, strided over CTAs
#define EPS 1e-5f

// Scratch (allocations forbidden)
__device__ float g_psum[NBLK * F_COLS];   // [slot][col] per-CTA partial sums  (2.4 MB)
__device__ float g_psqr[NBLK * F_COLS];   // [slot][col] per-CTA partial sumsq (2.4 MB)
__device__ float g_mean[F_COLS];
__device__ float g_rstd[F_COLS];

// Grid barrier (generation counter: replay-safe, wraparound-safe)
__device__ unsigned g_count = 0;
__device__ volatile unsigned g_gen = 0;

__device__ __forceinline__ void grid_barrier(unsigned nblocks) {
    __syncthreads();
    if (threadIdx.x == 0) {
        unsigned gen = g_gen;                    // read BEFORE arriving
        __threadfence();                         // publish this phase's writes
        unsigned arrived = atomicAdd(&g_count, 1u) + 1u;
        if (arrived == nblocks) {
            atomicExch(&g_count, 0u);
            __threadfence();
            g_gen = gen + 1u;                    // release
        } else {
            while (g_gen == gen) { __nanosleep(64); }
        }
        __threadfence();                         // acquire
    }
    __syncthreads();
}

// Coherent L2 loads for data written earlier in THIS launch. Never __ldg —
// its whole-kernel read-only promise lets the compiler hoist loads above the
// grid barrier (R6 failure mode).
__device__ __forceinline__ float4 ldcg4(const float4* p) {
    float4 v;
    asm volatile("ld.global.cg.v4.f32 {%0,%1,%2,%3}, [%4];"
                 : "=f"(v.x), "=f"(v.y), "=f"(v.z), "=f"(v.w) : "l"(p));
    return v;
}

// ---------------------------------------------------------------------------
// Fused persistent kernel, 592 CTAs = exactly 4 per SM (balanced phases).
// Phase 1 : accumulate own strided 8-row chunks (MLP_p1=8), one partial/CTA.
// Phase 2a: per-column mean/rstd from 592 partials (fixed order, L2-hot).
// Phase 2b: normalize own chunks in REVERSE phase-1 order (L2/L1 recency).
// ---------------------------------------------------------------------------
__global__ __launch_bounds__(256, 4) void msf_fused(const float* __restrict__ x,
                                                    const float* __restrict__ S_in,
                                                    float* __restrict__ out) {
    const int bid = blockIdx.x;
    const int t = threadIdx.x;                   // column group 0..255
    const float4* __restrict__ x4 = reinterpret_cast<const float4*>(x);
    float4* __restrict__ o4 = reinterpret_cast<float4*>(out);

    // ---------------- Phase 1: strided chunk partials ----------------------
    {
        float4 s = make_float4(0.f, 0.f, 0.f, 0.f);
        float4 q = make_float4(0.f, 0.f, 0.f, 0.f);

        for (int c = bid; c < NCHUNK; c += NBLK) {
            const size_t base = (size_t)c * CHUNK_ROWS * F4 + t;
            float4 v[8];
#pragma unroll
            for (int j = 0; j < 8; ++j)
                v[j] = __ldg(&x4[base + (size_t)j * F4]);   // x: true RO input
#pragma unroll
            for (int j = 0; j < 8; ++j) {
                s.x += v[j].x; s.y += v[j].y; s.z += v[j].z; s.w += v[j].w;
                q.x = fmaf(v[j].x, v[j].x, q.x);
                q.y = fmaf(v[j].y, v[j].y, q.y);
                q.z = fmaf(v[j].z, v[j].z, q.z);
                q.w = fmaf(v[j].w, v[j].w, q.w);
            }
        }
        __stcs(&reinterpret_cast<float4*>(g_psum)[bid * F4 + t], s);
        __stcs(&reinterpret_cast<float4*>(g_psqr)[bid * F4 + t], q);
    }

    grid_barrier(NBLK);

    // ---------------- Phase 2a: column stats (fixed order -> deterministic)
    {
        __shared__ float sh_s[256];
        __shared__ float sh_q[256];

        for (int col = bid; col < F_COLS; col += NBLK) {
            float s = 0.f, q = 0.f;
            for (int k = t; k < NBLK; k += 256) {        // k = t, t+256, (t+512)
                s += __ldcg(&g_psum[k * F_COLS + col]);  // coherent: same-launch data
                q += __ldcg(&g_psqr[k * F_COLS + col]);
            }
            sh_s[t] = s; sh_q[t] = q;
            __syncthreads();
#pragma unroll
            for (int w = 128; w > 0; w >>= 1) {
                if (t < w) { sh_s[t] += sh_s[t + w]; sh_q[t] += sh_q[t + w]; }
                __syncthreads();
            }
            if (t == 0) {
                const float n = (float)B_ROWS;
                float mean = sh_s[0] / n;
                float m2 = sh_q[0] - n * mean * mean + S_in[col];
                float var = m2 / (n - 1.0f);
                g_mean[col] = mean;
                g_rstd[col] = 1.0f / (sqrtf(var) + EPS);
            }
            __syncthreads();
        }
    }

    grid_barrier(NBLK);

    // ---------------- Phase 2b: normalize own chunks, reverse order --------
    {
        // Coherent loads (written in phase 2a of this launch): cannot be
        // hoisted above the barrier.
        const float4 m = ldcg4(&reinterpret_cast<const float4*>(g_mean)[t]);
        const float4 r = ldcg4(&reinterpret_cast<const float4*>(g_rstd)[t]);

        const int nchunks = (NCHUNK - 1 - bid) / NBLK + 1;
        for (int c = bid + (nchunks - 1) * NBLK; c >= 0; c -= NBLK) {
            const size_t base = (size_t)c * CHUNK_ROWS * F4 + t;
            float4 v[8];
#pragma unroll
            for (int j = 0; j < 8; ++j)
                v[j] = __ldcs(&x4[base + (size_t)j * F4]);
#pragma unroll
            for (int j = 0; j < 8; ++j) {
                float4 o;
                o.x = (v[j].x - m.x) * r.x;
                o.y = (v[j].y - m.y) * r.y;
                o.z = (v[j].z - m.z) * r.z;
                o.w = (v[j].w - m.w) * r.w;
                __stcs(&o4[base + (size_t)j * F4], o);
            }
        }
    }
}

extern "C" void kernel_launch(void* const* d_in, const int* in_sizes, int n_in,
                              void* d_out, int out_size) {
    const float* x    = (const float*)d_in[0];   // (32768, 1024) fp32
    // d_in[1] = running-mean buffer M: overwritten by first Welford sample -> unused
    const float* S_in = (const float*)d_in[2];   // (1024,) running M2, added into var
    float* out = (float*)d_out;

    msf_fused<<<NBLK, 256>>>(x, S_in, out);
}

// round 8
// speedup vs baseline: 1.0135x; 1.0135x over previous
#include <cuda_runtime.h>
#include <math.h>

// x is (B, F) row-major fp32
#define B_ROWS 32768
#define F_COLS 1024
#define F4     (F_COLS / 4)            // 256 float4 per row
#define NBLK   512                     // contiguous slices (R5 layout: best)
#define ROWS_PER_CTA (B_ROWS / NBLK)   // 64
#define HALF_ROWS 4
#define NHALF (ROWS_PER_CTA / HALF_ROWS)  // 16 half-chunks per CTA
#define EPS 1e-5f

// Scratch (allocations forbidden)
__device__ float g_psum[NBLK * F_COLS];   // [slot][col] partial sums   (2 MB)
__device__ float g_psqr[NBLK * F_COLS];   // [slot][col] partial sumsq  (2 MB)
__device__ float g_mean[F_COLS];
__device__ float g_rstd[F_COLS];

// Grid barrier (generation counter: replay-safe, wraparound-safe)
__device__ unsigned g_count = 0;
__device__ volatile unsigned g_gen = 0;

__device__ __forceinline__ void grid_barrier(unsigned nblocks) {
    __syncthreads();
    if (threadIdx.x == 0) {
        unsigned gen = g_gen;                    // read BEFORE arriving
        __threadfence();                         // publish this phase's writes
        unsigned arrived = atomicAdd(&g_count, 1u) + 1u;
        if (arrived == nblocks) {
            atomicExch(&g_count, 0u);
            __threadfence();
            g_gen = gen + 1u;                    // release
        } else {
            while (g_gen == gen) { __nanosleep(64); }
        }
        __threadfence();                         // acquire
    }
    __syncthreads();
}

// Coherent L2 load for data written earlier in THIS launch (never __ldg:
// its whole-kernel read-only promise allows hoisting above the barrier).
__device__ __forceinline__ float4 ldcg4(const float4* p) {
    float4 v;
    asm volatile("ld.global.cg.v4.f32 {%0,%1,%2,%3}, [%4];"
                 : "=f"(v.x), "=f"(v.y), "=f"(v.z), "=f"(v.w) : "l"(p));
    return v;
}

// ---------------------------------------------------------------------------
// Fused persistent kernel (512 CTAs, contiguous 64-row slices).
// Phase 1 : slice partials, 8-deep batched loads (MLP_p1=8).
// Phase 2a: per-column stats (coherent reads, fixed order).
// Phase 2b: normalize slice BACKWARD with a SOFTWARE-PIPELINED 2-buffer
//           rotation: loads of half-chunk h-2 issue between the store bursts
//           of h and h-1, so 8 loads stay in flight across the 12-cyc STG.128
//           issue bursts.
// ---------------------------------------------------------------------------
__global__ __launch_bounds__(256, 4) void msf_fused(const float* __restrict__ x,
                                                    const float* __restrict__ S_in,
                                                    float* __restrict__ out) {
    const int bid = blockIdx.x;
    const int t = threadIdx.x;                   // column group 0..255
    const float4* __restrict__ x4 = reinterpret_cast<const float4*>(x);
    float4* __restrict__ o4 = reinterpret_cast<float4*>(out);

    // ---------------- Phase 1: slice partials ------------------------------
    {
        float4 s = make_float4(0.f, 0.f, 0.f, 0.f);
        float4 q = make_float4(0.f, 0.f, 0.f, 0.f);
        const size_t base = (size_t)bid * ROWS_PER_CTA * F4 + t;

#pragma unroll
        for (int g = 0; g < ROWS_PER_CTA / 8; ++g) {
            float4 v[8];
#pragma unroll
            for (int j = 0; j < 8; ++j)
                v[j] = __ldg(&x4[base + (size_t)(g * 8 + j) * F4]);
#pragma unroll
            for (int j = 0; j < 8; ++j) {
                s.x += v[j].x; s.y += v[j].y; s.z += v[j].z; s.w += v[j].w;
                q.x = fmaf(v[j].x, v[j].x, q.x);
                q.y = fmaf(v[j].y, v[j].y, q.y);
                q.z = fmaf(v[j].z, v[j].z, q.z);
                q.w = fmaf(v[j].w, v[j].w, q.w);
            }
        }
        __stcs(&reinterpret_cast<float4*>(g_psum)[bid * F4 + t], s);
        __stcs(&reinterpret_cast<float4*>(g_psqr)[bid * F4 + t], q);
    }

    grid_barrier(NBLK);

    // ---------------- Phase 2a: stats for my 2 columns ---------------------
    {
        __shared__ float sh_s[256];
        __shared__ float sh_q[256];
        const int half = t >> 7;              // 0 or 1
        const int tt = t & 127;               // lane within half
        const int col = bid * 2 + half;

        float s = 0.f, q = 0.f;
#pragma unroll
        for (int k = 0; k < NBLK / 128; ++k) {      // 4 partials per thread
            const int c = k * 128 + tt;
            s += __ldcg(&g_psum[c * F_COLS + col]); // coherent: same-launch data
            q += __ldcg(&g_psqr[c * F_COLS + col]);
        }
        sh_s[t] = s; sh_q[t] = q;
        __syncthreads();
#pragma unroll
        for (int w = 64; w > 0; w >>= 1) {
            if (tt < w) { sh_s[t] += sh_s[t + w]; sh_q[t] += sh_q[t + w]; }
            __syncthreads();
        }
        if (tt == 0) {
            const float n = (float)B_ROWS;
            float mean = sh_s[half << 7] / n;
            float m2 = sh_q[half << 7] - n * mean * mean + S_in[col];
            float var = m2 / (n - 1.0f);
            g_mean[col] = mean;
            g_rstd[col] = 1.0f / (sqrtf(var) + EPS);
        }
    }

    grid_barrier(NBLK);

    // ---------------- Phase 2b: pipelined backward normalize ---------------
    {
        const float4 m = ldcg4(&reinterpret_cast<const float4*>(g_mean)[t]);
        const float4 r = ldcg4(&reinterpret_cast<const float4*>(g_rstd)[t]);
        const size_t sbase = (size_t)bid * ROWS_PER_CTA * F4 + t;

        float4 a[HALF_ROWS], b[HALF_ROWS];

        // addr(h, j) = sbase + (h*4 + j)*F4
#define LOAD4(buf, h)                                                          \
        {                                                                      \
            const size_t hb = sbase + (size_t)((h) * HALF_ROWS) * F4;          \
            _Pragma("unroll")                                                  \
            for (int j = 0; j < HALF_ROWS; ++j)                                \
                buf[j] = __ldcs(&x4[hb + (size_t)j * F4]);                     \
        }
#define STORE4(buf, h)                                                         \
        {                                                                      \
            const size_t hb = sbase + (size_t)((h) * HALF_ROWS) * F4;          \
            _Pragma("unroll")                                                  \
            for (int j = 0; j < HALF_ROWS; ++j) {                              \
                float4 o;                                                      \
                o.x = (buf[j].x - m.x) * r.x;                                  \
                o.y = (buf[j].y - m.y) * r.y;                                  \
                o.z = (buf[j].z - m.z) * r.z;                                  \
                o.w = (buf[j].w - m.w) * r.w;                                  \
                __stcs(&o4[hb + (size_t)j * F4], o);                           \
            }                                                                  \
        }

        // Backward: slice tail (read last in phase 1) is L2/L1-hot.
        LOAD4(a, NHALF - 1);
        LOAD4(b, NHALF - 2);
#pragma unroll
        for (int h = NHALF - 1; h >= 3; h -= 2) {
            STORE4(a, h);          // a(h) has arrived; store burst
            LOAD4(a, h - 2);       // refill while b(h-1) still in flight
            STORE4(b, h - 1);
            LOAD4(b, h - 3);       // refill while a(h-2) in flight
        }
        STORE4(a, 1);
        STORE4(b, 0);
#undef LOAD4
#undef STORE4
    }
}

extern "C" void kernel_launch(void* const* d_in, const int* in_sizes, int n_in,
                              void* d_out, int out_size) {
    const float* x    = (const float*)d_in[0];   // (32768, 1024) fp32
    // d_in[1] = running-mean buffer M: overwritten by first Welford sample -> unused
    const float* S_in = (const float*)d_in[2];   // (1024,) running M2, added into var
    float* out = (float*)d_out;

    msf_fused<<<NBLK, 256>>>(x, S_in, out);
}

// round 9
// speedup vs baseline: 1.0374x; 1.0235x over previous
#include <cuda_runtime.h>
#include <math.h>

// x is (B, F) row-major fp32
#define B_ROWS 32768
#define F_COLS 1024
#define F4     (F_COLS / 4)            // 256 float4 per row
#define NBLK   512                     // contiguous 64-row slices
#define ROWS_PER_CTA (B_ROWS / NBLK)   // 64
#define STASH_ROWS 8                   // rows 0..7 of each slice live in SMEM
#define GROUP_ROWS 4
#define NGRP ((ROWS_PER_CTA - STASH_ROWS) / GROUP_ROWS)   // 14 groups (rows 8..63)
#define EPS 1e-5f

// Scratch (allocations forbidden)
__device__ float g_psum[NBLK * F_COLS];   // [slot][col] partial sums   (2 MB)
__device__ float g_psqr[NBLK * F_COLS];   // [slot][col] partial sumsq  (2 MB)
__device__ float g_mean[F_COLS];
__device__ float g_rstd[F_COLS];

// Grid barrier (generation counter: replay-safe, wraparound-safe)
__device__ unsigned g_count = 0;
__device__ volatile unsigned g_gen = 0;

__device__ __forceinline__ void grid_barrier(unsigned nblocks) {
    __syncthreads();
    if (threadIdx.x == 0) {
        unsigned gen = g_gen;                    // read BEFORE arriving
        __threadfence();                         // publish this phase's writes
        unsigned arrived = atomicAdd(&g_count, 1u) + 1u;
        if (arrived == nblocks) {
            atomicExch(&g_count, 0u);
            __threadfence();
            g_gen = gen + 1u;                    // release
        } else {
            while (g_gen == gen) { __nanosleep(64); }
        }
        __threadfence();                         // acquire
    }
    __syncthreads();
}

// Coherent L2 load for data written earlier in THIS launch (never __ldg:
// its whole-kernel read-only promise allows hoisting above the barrier).
__device__ __forceinline__ float4 ldcg4(const float4* p) {
    float4 v;
    asm volatile("ld.global.cg.v4.f32 {%0,%1,%2,%3}, [%4];"
                 : "=f"(v.x), "=f"(v.y), "=f"(v.z), "=f"(v.w) : "l"(p));
    return v;
}

// ---------------------------------------------------------------------------
// Fused persistent kernel. Key insight: the kernel is LTS-bound (L2 hits cost
// the same LTS bandwidth as DRAM reads), so the phase-2b re-read must be
// served from SMEM/L1 (which bypass LTS) wherever possible.
// Phase 1 : slice partials (MLP=8); rows 0..7 additionally stashed in SMEM.
// Phase 2a: per-column stats (coherent reads, fixed order -> deterministic).
// Phase 2b: rows 63..8 normalized from global (backward, pipelined; slice
//           tail may hit L1D which persists within the launch); rows 7..0
//           normalized from the SMEM stash (zero LTS traffic).
// ---------------------------------------------------------------------------
__global__ __launch_bounds__(256, 4) void msf_fused(const float* __restrict__ x,
                                                    const float* __restrict__ S_in,
                                                    float* __restrict__ out) {
    __shared__ float4 stash[STASH_ROWS][256];    // 32 KB
    __shared__ float sh_s[256];                  // 1 KB
    __shared__ float sh_q[256];                  // 1 KB

    const int bid = blockIdx.x;
    const int t = threadIdx.x;                   // column group 0..255
    const float4* __restrict__ x4 = reinterpret_cast<const float4*>(x);
    float4* __restrict__ o4 = reinterpret_cast<float4*>(out);
    const size_t sbase = (size_t)bid * ROWS_PER_CTA * F4 + t;

    // ---------------- Phase 1: slice partials (+ stash rows 0..7) ----------
    {
        float4 s = make_float4(0.f, 0.f, 0.f, 0.f);
        float4 q = make_float4(0.f, 0.f, 0.f, 0.f);

#pragma unroll
        for (int g = 0; g < ROWS_PER_CTA / 8; ++g) {
            float4 v[8];
#pragma unroll
            for (int j = 0; j < 8; ++j)
                v[j] = __ldg(&x4[sbase + (size_t)(g * 8 + j) * F4]);
            if (g == 0) {                        // compile-time: first 8 rows
#pragma unroll
                for (int j = 0; j < 8; ++j)
                    stash[j][t] = v[j];
            }
#pragma unroll
            for (int j = 0; j < 8; ++j) {
                s.x += v[j].x; s.y += v[j].y; s.z += v[j].z; s.w += v[j].w;
                q.x = fmaf(v[j].x, v[j].x, q.x);
                q.y = fmaf(v[j].y, v[j].y, q.y);
                q.z = fmaf(v[j].z, v[j].z, q.z);
                q.w = fmaf(v[j].w, v[j].w, q.w);
            }
        }
        __stcs(&reinterpret_cast<float4*>(g_psum)[bid * F4 + t], s);
        __stcs(&reinterpret_cast<float4*>(g_psqr)[bid * F4 + t], q);
    }

    grid_barrier(NBLK);

    // ---------------- Phase 2a: stats for my 2 columns ---------------------
    {
        const int half = t >> 7;              // 0 or 1
        const int tt = t & 127;               // lane within half
        const int col = bid * 2 + half;

        float s = 0.f, q = 0.f;
#pragma unroll
        for (int k = 0; k < NBLK / 128; ++k) {      // 4 partials per thread
            const int c = k * 128 + tt;
            s += __ldcg(&g_psum[c * F_COLS + col]); // coherent: same-launch data
            q += __ldcg(&g_psqr[c * F_COLS + col]);
        }
        sh_s[t] = s; sh_q[t] = q;
        __syncthreads();
#pragma unroll
        for (int w = 64; w > 0; w >>= 1) {
            if (tt < w) { sh_s[t] += sh_s[t + w]; sh_q[t] += sh_q[t + w]; }
            __syncthreads();
        }
        if (tt == 0) {
            const float n = (float)B_ROWS;
            float mean = sh_s[half << 7] / n;
            float m2 = sh_q[half << 7] - n * mean * mean + S_in[col];
            float var = m2 / (n - 1.0f);
            g_mean[col] = mean;
            g_rstd[col] = 1.0f / (sqrtf(var) + EPS);
        }
    }

    grid_barrier(NBLK);

    // ---------------- Phase 2b: normalize ----------------------------------
    {
        const float4 m = ldcg4(&reinterpret_cast<const float4*>(g_mean)[t]);
        const float4 r = ldcg4(&reinterpret_cast<const float4*>(g_rstd)[t]);

        float4 a[GROUP_ROWS], b[GROUP_ROWS];

        // group h covers rows STASH_ROWS + h*4 .. +3 ; h in [0, NGRP)
#define LOAD4(buf, h)                                                          \
        {                                                                      \
            const size_t hb = sbase +                                          \
                (size_t)(STASH_ROWS + (h) * GROUP_ROWS) * F4;                  \
            _Pragma("unroll")                                                  \
            for (int j = 0; j < GROUP_ROWS; ++j)                               \
                buf[j] = __ldcs(&x4[hb + (size_t)j * F4]);                     \
        }
#define STORE4(buf, h)                                                         \
        {                                                                      \
            const size_t hb = sbase +                                          \
                (size_t)(STASH_ROWS + (h) * GROUP_ROWS) * F4;                  \
            _Pragma("unroll")                                                  \
            for (int j = 0; j < GROUP_ROWS; ++j) {                             \
                float4 o;                                                      \
                o.x = (buf[j].x - m.x) * r.x;                                  \
                o.y = (buf[j].y - m.y) * r.y;                                  \
                o.z = (buf[j].z - m.z) * r.z;                                  \
                o.w = (buf[j].w - m.w) * r.w;                                  \
                __stcs(&o4[hb + (size_t)j * F4], o);                           \
            }                                                                  \
        }

        // Backward over 14 global groups: tail was read last in phase 1
        // (L1D persists within the launch -> some LTS-free hits).
        LOAD4(a, NGRP - 1);
        LOAD4(b, NGRP - 2);
#pragma unroll
        for (int h = NGRP - 1; h >= 3; h -= 2) {
            STORE4(a, h);
            LOAD4(a, h - 2);
            STORE4(b, h - 1);
            LOAD4(b, h - 3);
        }
        STORE4(a, 1);
        STORE4(b, 0);
#undef LOAD4
#undef STORE4

        // Rows 0..7 from the SMEM stash: zero LTS read traffic.
#pragma unroll
        for (int j = 0; j < STASH_ROWS; ++j) {
            float4 v = stash[j][t];
            float4 o;
            o.x = (v.x - m.x) * r.x;
            o.y = (v.y - m.y) * r.y;
            o.z = (v.z - m.z) * r.z;
            o.w = (v.w - m.w) * r.w;
            __stcs(&o4[sbase + (size_t)j * F4], o);
        }
    }
}

extern "C" void kernel_launch(void* const* d_in, const int* in_sizes, int n_in,
                              void* d_out, int out_size) {
    const float* x    = (const float*)d_in[0];   // (32768, 1024) fp32
    // d_in[1] = running-mean buffer M: overwritten by first Welford sample -> unused
    const float* S_in = (const float*)d_in[2];   // (1024,) running M2, added into var
    float* out = (float*)d_out;

    msf_fused<<<NBLK, 256>>>(x, S_in, out);
}